// round 11
// baseline (speedup 1.0000x reference)
#include <cuda_runtime.h>
#include <cstdint>

#define NNODES 50000
#define NEDGES 800000
#define CDIM 256
#define FIN 768

#define BM 128
#define BN 128
#define KCH 16
#define PITCH 20                  // floats; conflict-free fragment loads
#define BUFB (BM * PITCH * 4)     // bytes per stage buffer

// Scratch (allocation-free rule: device globals)
__device__ float g_dinv[NNODES];
__device__ int   g_deg[NNODES];
__device__ int   g_off[NNODES + 1];
__device__ int   g_cur[NNODES];
__device__ int   g_csrc[NEDGES];
__device__ float g_hs [NNODES * CDIM];   // GEMM output h (unscaled)
__device__ float g_h1 [NNODES * CDIM];   // layer-1 activation
__device__ float g_WT1[CDIM * FIN];      // W1^T, tf32(rna)-rounded
__device__ float g_WT2[CDIM * CDIM];     // W2^T, tf32(rna)-rounded

__device__ __forceinline__ uint32_t smem_u32(const void* p) {
    uint32_t a;
    asm("{ .reg .u64 t; cvta.to.shared.u64 t, %1; cvt.u32.u64 %0, t; }"
        : "=r"(a) : "l"(p));
    return a;
}
__device__ __forceinline__ uint32_t f2tf32(float f) {
    uint32_t u;
    asm("cvt.rna.tf32.f32 %0, %1;" : "=r"(u) : "f"(f));
    return u;
}
__device__ __forceinline__ void mma_tf32(float* c, const uint32_t* a, const uint32_t* b) {
    asm volatile(
        "mma.sync.aligned.m16n8k8.row.col.f32.tf32.tf32.f32 "
        "{%0,%1,%2,%3}, {%4,%5,%6,%7}, {%8,%9}, {%0,%1,%2,%3};"
        : "+f"(c[0]), "+f"(c[1]), "+f"(c[2]), "+f"(c[3])
        : "r"(a[0]), "r"(a[1]), "r"(a[2]), "r"(a[3]), "r"(b[0]), "r"(b[1]));
}

// ---------------------------------------------------------------------------
__global__ void zero_int_k(int* __restrict__ p, int n) {
    int i = blockIdx.x * blockDim.x + threadIdx.x;
    if (i < n) p[i] = 0;
}
__global__ void degree_k(const int* __restrict__ dst, int E4) {
    int i = blockIdx.x * blockDim.x + threadIdx.x;
    if (i < E4) {
        int4 d = reinterpret_cast<const int4*>(dst)[i];
        atomicAdd(&g_deg[d.x], 1);
        atomicAdd(&g_deg[d.y], 1);
        atomicAdd(&g_deg[d.z], 1);
        atomicAdd(&g_deg[d.w], 1);
    }
}
__global__ void dinv_k(int n) {
    int i = blockIdx.x * blockDim.x + threadIdx.x;
    if (i < n) g_dinv[i] = rsqrtf((float)g_deg[i] + 1.0f);  // +1 = self loop
}

__global__ void scan_k() {
    __shared__ int sums[1024];
    const int T = 1024;
    const int chunk = (NNODES + T - 1) / T;
    int t = threadIdx.x;
    int base = t * chunk;
    int s = 0;
    for (int j = 0; j < chunk; j++) {
        int i = base + j;
        if (i < NNODES) s += g_deg[i];
    }
    sums[t] = s;
    __syncthreads();
    for (int d = 1; d < T; d <<= 1) {
        int v = (t >= d) ? sums[t - d] : 0;
        __syncthreads();
        sums[t] += v;
        __syncthreads();
    }
    int run = (t == 0) ? 0 : sums[t - 1];
    for (int j = 0; j < chunk; j++) {
        int i = base + j;
        if (i < NNODES) {
            g_off[i] = run;
            g_cur[i] = run;
            run += g_deg[i];
        }
    }
    if (t == T - 1) g_off[NNODES] = run;
}

__global__ void csr_fill_k(const int* __restrict__ src,
                           const int* __restrict__ dst, int E) {
    int e = blockIdx.x * blockDim.x + threadIdx.x;
    if (e < E) {
        int p = atomicAdd(&g_cur[dst[e]], 1);
        g_csrc[p] = src[e];
    }
}

// Both weight transposes in ONE launch (keeps gemm1 in the ncu capture slot).
__global__ void transpose_both_k(const float* __restrict__ W1,
                                 const float* __restrict__ W2) {
    int idx = blockIdx.x * blockDim.x + threadIdx.x;
    if (idx < FIN * CDIM) {
        int n = idx & (CDIM - 1);
        int k = idx >> 8;
        g_WT1[(size_t)n * FIN + k] =
            __uint_as_float(f2tf32(W1[(size_t)k * CDIM + n]));
    } else {
        idx -= FIN * CDIM;
        if (idx < CDIM * CDIM) {
            int n = idx & (CDIM - 1);
            int k = idx >> 8;
            g_WT2[(size_t)n * CDIM + k] =
                __uint_as_float(f2tf32(W2[(size_t)k * CDIM + n]));
        }
    }
}

// ---------------------------------------------------------------------------
// C[M,256] = A[M,K] @ WT^T  (dinv applied in agg_k)
// 128x128 CTA tile, 8 warps (2x4), 64x32 warp tiles, cp.async 2-stage.
// A operand passed as raw fp32 bits: tf32 MMA HW reads the top 19 bits
// (truncation) — no per-fragment cvt in the mainloop.
// ---------------------------------------------------------------------------
__global__ __launch_bounds__(256, 2) void gemm_mma_k(
    const float* __restrict__ A, const float* __restrict__ WT,
    float* __restrict__ C, int M, int K)
{
    __shared__ float As[2][BM * PITCH];
    __shared__ float Bs[2][BN * PITCH];

    const int tid  = threadIdx.x;
    const int lane = tid & 31;
    const int wid  = tid >> 5;
    const int wm   = wid & 1;
    const int wn   = wid >> 1;
    const int gq   = lane >> 2;
    const int cq   = lane & 3;
    const int row0 = blockIdx.y * BM;
    const int col0 = blockIdx.x * BN;

    const uint32_t asb = smem_u32(&As[0][0]);
    const uint32_t bsb = smem_u32(&Bs[0][0]);

    float acc[4][4][4];
    #pragma unroll
    for (int mt = 0; mt < 4; mt++)
        #pragma unroll
        for (int nt = 0; nt < 4; nt++)
            #pragma unroll
            for (int q = 0; q < 4; q++) acc[mt][nt][q] = 0.f;

    const int nkc = K / KCH;

    auto issue = [&](int kc, int buf) {
        const int koff = kc * KCH;
        #pragma unroll
        for (int t = 0; t < 2; t++) {
            int idx = tid + t * 256;
            int r   = idx >> 2;
            int kq  = (idx & 3) * 4;
            uint32_t soff = (uint32_t)((r * PITCH + kq) * 4) + (uint32_t)buf * BUFB;
            int gr = row0 + r;
            const float* srcA = A + (size_t)(gr < M ? gr : M - 1) * K + koff + kq;
            int nb = (gr < M) ? 16 : 0;
            asm volatile("cp.async.ca.shared.global [%0], [%1], 16, %2;"
                         :: "r"(asb + soff), "l"(srcA), "r"(nb));
            const float* srcB = WT + (size_t)(col0 + r) * K + koff + kq;
            asm volatile("cp.async.ca.shared.global [%0], [%1], 16;"
                         :: "r"(bsb + soff), "l"(srcB));
        }
        asm volatile("cp.async.commit_group;" ::: "memory");
    };

    issue(0, 0);

    for (int kc = 0; kc < nkc; kc++) {
        const int cur = kc & 1;
        const bool more = (kc + 1) < nkc;
        if (more) {
            issue(kc + 1, cur ^ 1);
            asm volatile("cp.async.wait_group 1;" ::: "memory");
        } else {
            asm volatile("cp.async.wait_group 0;" ::: "memory");
        }
        __syncthreads();

        #pragma unroll
        for (int k0 = 0; k0 < KCH; k0 += 8) {
            uint32_t bf[4][2];
            #pragma unroll
            for (int nt = 0; nt < 4; nt++) {
                int n = wn * 32 + nt * 8 + gq;
                bf[nt][0] = __float_as_uint(Bs[cur][n * PITCH + k0 + cq]);
                bf[nt][1] = __float_as_uint(Bs[cur][n * PITCH + k0 + cq + 4]);
            }
            #pragma unroll
            for (int mt = 0; mt < 4; mt++) {
                int r = wm * 64 + mt * 16 + gq;
                uint32_t af[4];
                af[0] = __float_as_uint(As[cur][(r    ) * PITCH + k0 + cq    ]);
                af[1] = __float_as_uint(As[cur][(r + 8) * PITCH + k0 + cq    ]);
                af[2] = __float_as_uint(As[cur][(r    ) * PITCH + k0 + cq + 4]);
                af[3] = __float_as_uint(As[cur][(r + 8) * PITCH + k0 + cq + 4]);
                #pragma unroll
                for (int nt = 0; nt < 4; nt++)
                    mma_tf32(acc[mt][nt], af, bf[nt]);
            }
        }
        __syncthreads();
    }

    #pragma unroll
    for (int mt = 0; mt < 4; mt++) {
        #pragma unroll
        for (int h = 0; h < 2; h++) {
            int row = row0 + wm * 64 + mt * 16 + gq + h * 8;
            if (row < M) {
                float* cp = C + (size_t)row * CDIM + col0 + wn * 32;
                #pragma unroll
                for (int nt = 0; nt < 4; nt++) {
                    float2 o;
                    o.x = acc[mt][nt][h * 2 + 0];
                    o.y = acc[mt][nt][h * 2 + 1];
                    *reinterpret_cast<float2*>(cp + nt * 8 + cq * 2) = o;
                }
            }
        }
    }
}

// ---------------------------------------------------------------------------
// Fused CSR gather with per-edge dinv[src] + self-loop + dinv[dst] + bias
// ---------------------------------------------------------------------------
__global__ __launch_bounds__(256) void agg_k(const float* __restrict__ b,
                                             float* __restrict__ out,
                                             int relu)
{
    int node = blockIdx.x * 4 + (threadIdx.x >> 6);
    if (node >= NNODES) return;
    int lane = threadIdx.x & 63;

    const float4* hs4 = reinterpret_cast<const float4*>(g_hs);
    float di = g_dinv[node];
    float4 self = hs4[(size_t)node * 64 + lane];
    float4 acc;
    acc.x = self.x * di; acc.y = self.y * di;
    acc.z = self.z * di; acc.w = self.w * di;

    int j   = g_off[node];
    int end = g_off[node + 1];
    for (; j + 1 < end; j += 2) {
        int s0 = g_csrc[j];
        int s1 = g_csrc[j + 1];
        float d0 = g_dinv[s0];
        float d1 = g_dinv[s1];
        float4 v0 = hs4[(size_t)s0 * 64 + lane];
        float4 v1 = hs4[(size_t)s1 * 64 + lane];
        acc.x = fmaf(v0.x, d0, acc.x); acc.y = fmaf(v0.y, d0, acc.y);
        acc.z = fmaf(v0.z, d0, acc.z); acc.w = fmaf(v0.w, d0, acc.w);
        acc.x = fmaf(v1.x, d1, acc.x); acc.y = fmaf(v1.y, d1, acc.y);
        acc.z = fmaf(v1.z, d1, acc.z); acc.w = fmaf(v1.w, d1, acc.w);
    }
    if (j < end) {
        int s0 = g_csrc[j];
        float d0 = g_dinv[s0];
        float4 v0 = hs4[(size_t)s0 * 64 + lane];
        acc.x = fmaf(v0.x, d0, acc.x); acc.y = fmaf(v0.y, d0, acc.y);
        acc.z = fmaf(v0.z, d0, acc.z); acc.w = fmaf(v0.w, d0, acc.w);
    }

    const float4 bb = *reinterpret_cast<const float4*>(b + lane * 4);
    float4 o;
    o.x = fmaf(acc.x, di, bb.x);
    o.y = fmaf(acc.y, di, bb.y);
    o.z = fmaf(acc.z, di, bb.z);
    o.w = fmaf(acc.w, di, bb.w);
    if (relu) {
        o.x = fmaxf(o.x, 0.f); o.y = fmaxf(o.y, 0.f);
        o.z = fmaxf(o.z, 0.f); o.w = fmaxf(o.w, 0.f);
    }
    reinterpret_cast<float4*>(out)[(size_t)node * 64 + lane] = o;
}

// ---------------------------------------------------------------------------
extern "C" void kernel_launch(void* const* d_in, const int* in_sizes, int n_in,
                              void* d_out, int out_size)
{
    const float* x  = (const float*)d_in[0];
    const int*   ei = (const int*)  d_in[1];
    const float* W1 = (const float*)d_in[2];
    const float* b1 = (const float*)d_in[3];
    const float* W2 = (const float*)d_in[4];
    const float* b2 = (const float*)d_in[5];
    (void)in_sizes; (void)n_in; (void)out_size;

    const int* src = ei;
    const int* dst = ei + NEDGES;

    float *hs, *h1, *wt1, *wt2;
    int* degp;
    cudaGetSymbolAddress((void**)&hs,  g_hs);
    cudaGetSymbolAddress((void**)&h1,  g_h1);
    cudaGetSymbolAddress((void**)&wt1, g_WT1);
    cudaGetSymbolAddress((void**)&wt2, g_WT2);
    cudaGetSymbolAddress((void**)&degp, g_deg);

    // Side stream + events for fork/join inside graph capture.
    static cudaStream_t sB = nullptr;
    static cudaEvent_t evFork = nullptr, evJoin = nullptr;
    if (!sB) {
        cudaStreamCreateWithFlags(&sB, cudaStreamNonBlocking);
        cudaEventCreateWithFlags(&evFork, cudaEventDisableTiming);
        cudaEventCreateWithFlags(&evJoin, cudaEventDisableTiming);
    }

    const dim3 gemm_grid(CDIM / BN, (NNODES + BM - 1) / BM);   // (2, 391)
    const int agg_grid = (NNODES + 3) / 4;

    // Fork side stream off the main (capturing) stream.
    cudaEventRecord(evFork, 0);
    cudaStreamWaitEvent(sB, evFork, 0);

    // Main: weights + GEMM1.  Side: CSR/degree preprocessing (independent).
    transpose_both_k<<<((FIN + CDIM) * CDIM + 255) / 256, 256>>>(W1, W2);      // 0 main
    zero_int_k<<<(NNODES + 255) / 256, 256, 0, sB>>>(degp, NNODES);            // 1 side
    degree_k  <<<(NEDGES / 4 + 255) / 256, 256, 0, sB>>>(dst, NEDGES / 4);     // 2 side
    gemm_mma_k<<<gemm_grid, 256>>>(x, wt1, hs, NNODES, FIN);                   // 3 main <- ncu
    dinv_k    <<<(NNODES + 255) / 256, 256, 0, sB>>>(NNODES);                  // 4 side
    scan_k    <<<1, 1024, 0, sB>>>();                                          // 5 side
    csr_fill_k<<<(NEDGES + 255) / 256, 256, 0, sB>>>(src, dst, NEDGES);        // 6 side

    // Join: agg1 needs CSR + dinv + hs.
    cudaEventRecord(evJoin, sB);
    cudaStreamWaitEvent(0, evJoin, 0);

    agg_k<<<agg_grid, 256>>>(b1, h1, 1);                                       // 7
    gemm_mma_k<<<gemm_grid, 256>>>(h1, wt2, hs, NNODES, CDIM);                 // 8
    agg_k<<<agg_grid, 256>>>(b2, (float*)d_out, 0);                            // 9
}

// round 12
// speedup vs baseline: 1.0495x; 1.0495x over previous
#include <cuda_runtime.h>
#include <cuda_fp16.h>
#include <cstdint>

#define NNODES 50000
#define NEDGES 800000
#define CDIM 256
#define FIN 768

#define BM 128
#define BN 128
#define KCH 16
#define PITCH 20                  // floats; conflict-free fragment loads
#define BUFB (BM * PITCH * 4)     // bytes per stage buffer

// Scratch (allocation-free rule: device globals)
__device__ float  g_dinv[NNODES];
__device__ int    g_deg[NNODES];
__device__ int    g_off[NNODES + 1];
__device__ int    g_cur[NNODES];
__device__ int    g_csrc[NEDGES];
__device__ __half g_hsh[NNODES * CDIM];  // GEMM output h, fp16 (gather payload)
__device__ float  g_h1 [NNODES * CDIM];  // layer-1 activation (tf32-rounded)
__device__ float  g_WT1[CDIM * FIN];     // W1^T, tf32(rna)
__device__ float  g_WT2[CDIM * CDIM];    // W2^T, tf32(rna)

__device__ __forceinline__ uint32_t smem_u32(const void* p) {
    uint32_t a;
    asm("{ .reg .u64 t; cvta.to.shared.u64 t, %1; cvt.u32.u64 %0, t; }"
        : "=r"(a) : "l"(p));
    return a;
}
__device__ __forceinline__ uint32_t f2tf32(float f) {
    uint32_t u;
    asm("cvt.rna.tf32.f32 %0, %1;" : "=r"(u) : "f"(f));
    return u;
}
__device__ __forceinline__ void mma_tf32(float* c, const uint32_t* a, const uint32_t* b) {
    asm volatile(
        "mma.sync.aligned.m16n8k8.row.col.f32.tf32.tf32.f32 "
        "{%0,%1,%2,%3}, {%4,%5,%6,%7}, {%8,%9}, {%0,%1,%2,%3};"
        : "+f"(c[0]), "+f"(c[1]), "+f"(c[2]), "+f"(c[3])
        : "r"(a[0]), "r"(a[1]), "r"(a[2]), "r"(a[3]), "r"(b[0]), "r"(b[1]));
}

// ---------------------------------------------------------------------------
__global__ void zero_int_k(int* __restrict__ p, int n) {
    int i = blockIdx.x * blockDim.x + threadIdx.x;
    if (i < n) p[i] = 0;
}
__global__ void degree_k(const int* __restrict__ dst, int E4) {
    int i = blockIdx.x * blockDim.x + threadIdx.x;
    if (i < E4) {
        int4 d = reinterpret_cast<const int4*>(dst)[i];
        atomicAdd(&g_deg[d.x], 1);
        atomicAdd(&g_deg[d.y], 1);
        atomicAdd(&g_deg[d.z], 1);
        atomicAdd(&g_deg[d.w], 1);
    }
}
__global__ void dinv_k(int n) {
    int i = blockIdx.x * blockDim.x + threadIdx.x;
    if (i < n) g_dinv[i] = rsqrtf((float)g_deg[i] + 1.0f);  // +1 = self loop
}

__global__ void scan_k() {
    __shared__ int sums[1024];
    const int T = 1024;
    const int chunk = (NNODES + T - 1) / T;
    int t = threadIdx.x;
    int base = t * chunk;
    int s = 0;
    for (int j = 0; j < chunk; j++) {
        int i = base + j;
        if (i < NNODES) s += g_deg[i];
    }
    sums[t] = s;
    __syncthreads();
    for (int d = 1; d < T; d <<= 1) {
        int v = (t >= d) ? sums[t - d] : 0;
        __syncthreads();
        sums[t] += v;
        __syncthreads();
    }
    int run = (t == 0) ? 0 : sums[t - 1];
    for (int j = 0; j < chunk; j++) {
        int i = base + j;
        if (i < NNODES) {
            g_off[i] = run;
            g_cur[i] = run;
            run += g_deg[i];
        }
    }
    if (t == T - 1) g_off[NNODES] = run;
}

__global__ void csr_fill_k(const int* __restrict__ src,
                           const int* __restrict__ dst, int E) {
    int e = blockIdx.x * blockDim.x + threadIdx.x;
    if (e < E) {
        int p = atomicAdd(&g_cur[dst[e]], 1);
        g_csrc[p] = src[e];
    }
}

// Both weight transposes in ONE launch (keeps gemm1 in the ncu capture slot).
__global__ void transpose_both_k(const float* __restrict__ W1,
                                 const float* __restrict__ W2) {
    int idx = blockIdx.x * blockDim.x + threadIdx.x;
    if (idx < FIN * CDIM) {
        int n = idx & (CDIM - 1);
        int k = idx >> 8;
        g_WT1[(size_t)n * FIN + k] =
            __uint_as_float(f2tf32(W1[(size_t)k * CDIM + n]));
    } else {
        idx -= FIN * CDIM;
        if (idx < CDIM * CDIM) {
            int n = idx & (CDIM - 1);
            int k = idx >> 8;
            g_WT2[(size_t)n * CDIM + k] =
                __uint_as_float(f2tf32(W2[(size_t)k * CDIM + n]));
        }
    }
}

// ---------------------------------------------------------------------------
// Ch[M,256](fp16) = A[M,K] @ WT^T   (dinv applied in agg_k)
// 128x128 CTA tile, 8 warps (2x4), 64x32 warp tiles, cp.async 2-stage.
// CVT=true: rna-round A fragments to tf32 (layer 1; layer-2 A pre-rounded).
// ---------------------------------------------------------------------------
template <bool CVT>
__global__ __launch_bounds__(256, 2) void gemm_mma_k(
    const float* __restrict__ A, const float* __restrict__ WT,
    __half* __restrict__ Ch, int M, int K)
{
    __shared__ float As[2][BM * PITCH];
    __shared__ float Bs[2][BN * PITCH];

    const int tid  = threadIdx.x;
    const int lane = tid & 31;
    const int wid  = tid >> 5;
    const int wm   = wid & 1;
    const int wn   = wid >> 1;
    const int gq   = lane >> 2;
    const int cq   = lane & 3;
    const int row0 = blockIdx.y * BM;
    const int col0 = blockIdx.x * BN;

    const uint32_t asb = smem_u32(&As[0][0]);
    const uint32_t bsb = smem_u32(&Bs[0][0]);

    float acc[4][4][4];
    #pragma unroll
    for (int mt = 0; mt < 4; mt++)
        #pragma unroll
        for (int nt = 0; nt < 4; nt++)
            #pragma unroll
            for (int q = 0; q < 4; q++) acc[mt][nt][q] = 0.f;

    const int nkc = K / KCH;

    auto issue = [&](int kc, int buf) {
        const int koff = kc * KCH;
        #pragma unroll
        for (int t = 0; t < 2; t++) {
            int idx = tid + t * 256;
            int r   = idx >> 2;
            int kq  = (idx & 3) * 4;
            uint32_t soff = (uint32_t)((r * PITCH + kq) * 4) + (uint32_t)buf * BUFB;
            int gr = row0 + r;
            const float* srcA = A + (size_t)(gr < M ? gr : M - 1) * K + koff + kq;
            int nb = (gr < M) ? 16 : 0;
            asm volatile("cp.async.ca.shared.global [%0], [%1], 16, %2;"
                         :: "r"(asb + soff), "l"(srcA), "r"(nb));
            const float* srcB = WT + (size_t)(col0 + r) * K + koff + kq;
            asm volatile("cp.async.ca.shared.global [%0], [%1], 16;"
                         :: "r"(bsb + soff), "l"(srcB));
        }
        asm volatile("cp.async.commit_group;" ::: "memory");
    };

    issue(0, 0);

    for (int kc = 0; kc < nkc; kc++) {
        const int cur = kc & 1;
        const bool more = (kc + 1) < nkc;
        if (more) {
            issue(kc + 1, cur ^ 1);
            asm volatile("cp.async.wait_group 1;" ::: "memory");
        } else {
            asm volatile("cp.async.wait_group 0;" ::: "memory");
        }
        __syncthreads();

        #pragma unroll
        for (int k0 = 0; k0 < KCH; k0 += 8) {
            uint32_t bf[4][2];
            #pragma unroll
            for (int nt = 0; nt < 4; nt++) {
                int n = wn * 32 + nt * 8 + gq;
                bf[nt][0] = __float_as_uint(Bs[cur][n * PITCH + k0 + cq]);
                bf[nt][1] = __float_as_uint(Bs[cur][n * PITCH + k0 + cq + 4]);
            }
            #pragma unroll
            for (int mt = 0; mt < 4; mt++) {
                int r = wm * 64 + mt * 16 + gq;
                uint32_t af[4];
                if (CVT) {
                    af[0] = f2tf32(As[cur][(r    ) * PITCH + k0 + cq    ]);
                    af[1] = f2tf32(As[cur][(r + 8) * PITCH + k0 + cq    ]);
                    af[2] = f2tf32(As[cur][(r    ) * PITCH + k0 + cq + 4]);
                    af[3] = f2tf32(As[cur][(r + 8) * PITCH + k0 + cq + 4]);
                } else {
                    af[0] = __float_as_uint(As[cur][(r    ) * PITCH + k0 + cq    ]);
                    af[1] = __float_as_uint(As[cur][(r + 8) * PITCH + k0 + cq    ]);
                    af[2] = __float_as_uint(As[cur][(r    ) * PITCH + k0 + cq + 4]);
                    af[3] = __float_as_uint(As[cur][(r + 8) * PITCH + k0 + cq + 4]);
                }
                #pragma unroll
                for (int nt = 0; nt < 4; nt++)
                    mma_tf32(acc[mt][nt], af, bf[nt]);
            }
        }
        __syncthreads();
    }

    // epilogue: store fp16 (half2 per register pair)
    #pragma unroll
    for (int mt = 0; mt < 4; mt++) {
        #pragma unroll
        for (int h = 0; h < 2; h++) {
            int row = row0 + wm * 64 + mt * 16 + gq + h * 8;
            if (row < M) {
                __half* cp = Ch + (size_t)row * CDIM + col0 + wn * 32;
                #pragma unroll
                for (int nt = 0; nt < 4; nt++) {
                    __half2 o = __floats2half2_rn(acc[mt][nt][h * 2 + 0],
                                                  acc[mt][nt][h * 2 + 1]);
                    *reinterpret_cast<__half2*>(cp + nt * 8 + cq * 2) = o;
                }
            }
        }
    }
}

// ---------------------------------------------------------------------------
// Fused CSR gather (fp16 rows) + per-edge dinv[src] + self-loop + dinv[dst]
// + bias (+relu +tf32-round). Accumulation in fp32.
// ---------------------------------------------------------------------------
__global__ __launch_bounds__(256) void agg_k(const float* __restrict__ b,
                                             float* __restrict__ out,
                                             int relu_round)
{
    int node = blockIdx.x * 4 + (threadIdx.x >> 6);
    if (node >= NNODES) return;
    int lane = threadIdx.x & 63;   // covers cols [lane*4, lane*4+4)

    const uint2* hs2 = reinterpret_cast<const uint2*>(g_hsh);  // 4 halfs per uint2
    float di = g_dinv[node];

    uint2 us = hs2[(size_t)node * 64 + lane];
    float2 s0 = __half22float2(*reinterpret_cast<__half2*>(&us.x));
    float2 s1 = __half22float2(*reinterpret_cast<__half2*>(&us.y));
    float4 acc;
    acc.x = s0.x * di; acc.y = s0.y * di;
    acc.z = s1.x * di; acc.w = s1.y * di;

    int j   = g_off[node];
    int end = g_off[node + 1];
    for (; j + 1 < end; j += 2) {
        int e0 = g_csrc[j];
        int e1 = g_csrc[j + 1];
        float d0 = g_dinv[e0];
        float d1 = g_dinv[e1];
        uint2 u0 = hs2[(size_t)e0 * 64 + lane];
        uint2 u1 = hs2[(size_t)e1 * 64 + lane];
        float2 a0 = __half22float2(*reinterpret_cast<__half2*>(&u0.x));
        float2 a1 = __half22float2(*reinterpret_cast<__half2*>(&u0.y));
        float2 c0 = __half22float2(*reinterpret_cast<__half2*>(&u1.x));
        float2 c1 = __half22float2(*reinterpret_cast<__half2*>(&u1.y));
        acc.x = fmaf(a0.x, d0, acc.x); acc.y = fmaf(a0.y, d0, acc.y);
        acc.z = fmaf(a1.x, d0, acc.z); acc.w = fmaf(a1.y, d0, acc.w);
        acc.x = fmaf(c0.x, d1, acc.x); acc.y = fmaf(c0.y, d1, acc.y);
        acc.z = fmaf(c1.x, d1, acc.z); acc.w = fmaf(c1.y, d1, acc.w);
    }
    if (j < end) {
        int e0 = g_csrc[j];
        float d0 = g_dinv[e0];
        uint2 u0 = hs2[(size_t)e0 * 64 + lane];
        float2 a0 = __half22float2(*reinterpret_cast<__half2*>(&u0.x));
        float2 a1 = __half22float2(*reinterpret_cast<__half2*>(&u0.y));
        acc.x = fmaf(a0.x, d0, acc.x); acc.y = fmaf(a0.y, d0, acc.y);
        acc.z = fmaf(a1.x, d0, acc.z); acc.w = fmaf(a1.y, d0, acc.w);
    }

    const float4 bb = *reinterpret_cast<const float4*>(b + lane * 4);
    float4 o;
    o.x = fmaf(acc.x, di, bb.x);
    o.y = fmaf(acc.y, di, bb.y);
    o.z = fmaf(acc.z, di, bb.z);
    o.w = fmaf(acc.w, di, bb.w);
    if (relu_round) {
        // relu then round to tf32 (next GEMM reads this as its A operand)
        o.x = __uint_as_float(f2tf32(fmaxf(o.x, 0.f)));
        o.y = __uint_as_float(f2tf32(fmaxf(o.y, 0.f)));
        o.z = __uint_as_float(f2tf32(fmaxf(o.z, 0.f)));
        o.w = __uint_as_float(f2tf32(fmaxf(o.w, 0.f)));
    }
    reinterpret_cast<float4*>(out)[(size_t)node * 64 + lane] = o;
}

// ---------------------------------------------------------------------------
extern "C" void kernel_launch(void* const* d_in, const int* in_sizes, int n_in,
                              void* d_out, int out_size)
{
    const float* x  = (const float*)d_in[0];
    const int*   ei = (const int*)  d_in[1];
    const float* W1 = (const float*)d_in[2];
    const float* b1 = (const float*)d_in[3];
    const float* W2 = (const float*)d_in[4];
    const float* b2 = (const float*)d_in[5];
    (void)in_sizes; (void)n_in; (void)out_size;

    const int* src = ei;
    const int* dst = ei + NEDGES;

    float *h1, *wt1, *wt2;
    __half* hsh;
    int* degp;
    cudaGetSymbolAddress((void**)&hsh, g_hsh);
    cudaGetSymbolAddress((void**)&h1,  g_h1);
    cudaGetSymbolAddress((void**)&wt1, g_WT1);
    cudaGetSymbolAddress((void**)&wt2, g_WT2);
    cudaGetSymbolAddress((void**)&degp, g_deg);

    // Side stream + events for fork/join inside graph capture.
    static cudaStream_t sB = nullptr;
    static cudaEvent_t evFork = nullptr, evJoin = nullptr;
    if (!sB) {
        cudaStreamCreateWithFlags(&sB, cudaStreamNonBlocking);
        cudaEventCreateWithFlags(&evFork, cudaEventDisableTiming);
        cudaEventCreateWithFlags(&evJoin, cudaEventDisableTiming);
    }

    const dim3 gemm_grid(CDIM / BN, (NNODES + BM - 1) / BM);   // (2, 391)
    const int agg_grid = (NNODES + 3) / 4;

    // Fork side stream off the main (capturing) stream.
    cudaEventRecord(evFork, 0);
    cudaStreamWaitEvent(sB, evFork, 0);

    // Main: weights + GEMM1.  Side: CSR/degree preprocessing (independent).
    transpose_both_k<<<((FIN + CDIM) * CDIM + 255) / 256, 256>>>(W1, W2);      // 0 main
    zero_int_k<<<(NNODES + 255) / 256, 256, 0, sB>>>(degp, NNODES);            // 1 side
    degree_k  <<<(NEDGES / 4 + 255) / 256, 256, 0, sB>>>(dst, NEDGES / 4);     // 2 side
    gemm_mma_k<true><<<gemm_grid, 256>>>(x, wt1, hsh, NNODES, FIN);            // 3 main <- ncu
    dinv_k    <<<(NNODES + 255) / 256, 256, 0, sB>>>(NNODES);                  // 4 side
    scan_k    <<<1, 1024, 0, sB>>>();                                          // 5 side
    csr_fill_k<<<(NEDGES + 255) / 256, 256, 0, sB>>>(src, dst, NEDGES);        // 6 side

    // Join: agg1 needs CSR + dinv + hs.
    cudaEventRecord(evJoin, sB);
    cudaStreamWaitEvent(0, evJoin, 0);

    agg_k<<<agg_grid, 256>>>(b1, h1, 1);                                       // 7
    gemm_mma_k<false><<<gemm_grid, 256>>>(h1, wt2, hsh, NNODES, CDIM);         // 8
    agg_k<<<agg_grid, 256>>>(b2, (float*)d_out, 0);                            // 9
}

// round 13
// speedup vs baseline: 1.1867x; 1.1308x over previous
#include <cuda_runtime.h>
#include <cuda_fp16.h>
#include <cstdint>

#define NNODES 50000
#define NEDGES 800000
#define CDIM 256
#define FIN 768

#define BM 128
#define BN 128
#define KCH 32                    // halfs per K-chunk (2 MMA steps of k16)
#define PITCH 20                  // uints (half2 pairs) per row; conflict-free
#define BUFB (BM * PITCH * 4)     // bytes per stage buffer (10240)

// Scratch (allocation-free rule: device globals)
__device__ float  g_dinv[NNODES];
__device__ int    g_deg[NNODES];
__device__ int    g_off[NNODES + 1];
__device__ int    g_cur[NNODES];
__device__ int    g_csrc[NEDGES];
__device__ __half g_xh [NNODES * FIN];   // x converted to fp16
__device__ __half g_hsh[NNODES * CDIM];  // GEMM output h, fp16 (gather payload)
__device__ __half g_h1h[NNODES * CDIM];  // layer-1 activation, fp16
__device__ __half g_WT1[CDIM * FIN];     // W1^T fp16
__device__ __half g_WT2[CDIM * CDIM];    // W2^T fp16

__device__ __forceinline__ uint32_t smem_u32(const void* p) {
    uint32_t a;
    asm("{ .reg .u64 t; cvta.to.shared.u64 t, %1; cvt.u32.u64 %0, t; }"
        : "=r"(a) : "l"(p));
    return a;
}
__device__ __forceinline__ void mma_f16(float* c, const uint32_t* a, const uint32_t* b) {
    asm volatile(
        "mma.sync.aligned.m16n8k16.row.col.f32.f16.f16.f32 "
        "{%0,%1,%2,%3}, {%4,%5,%6,%7}, {%8,%9}, {%0,%1,%2,%3};"
        : "+f"(c[0]), "+f"(c[1]), "+f"(c[2]), "+f"(c[3])
        : "r"(a[0]), "r"(a[1]), "r"(a[2]), "r"(a[3]), "r"(b[0]), "r"(b[1]));
}

// ---------------------------------------------------------------------------
__global__ void zero_int_k(int* __restrict__ p, int n) {
    int i = blockIdx.x * blockDim.x + threadIdx.x;
    if (i < n) p[i] = 0;
}
__global__ void degree_k(const int* __restrict__ dst, int E4) {
    int i = blockIdx.x * blockDim.x + threadIdx.x;
    if (i < E4) {
        int4 d = reinterpret_cast<const int4*>(dst)[i];
        atomicAdd(&g_deg[d.x], 1);
        atomicAdd(&g_deg[d.y], 1);
        atomicAdd(&g_deg[d.z], 1);
        atomicAdd(&g_deg[d.w], 1);
    }
}
__global__ void dinv_k(int n) {
    int i = blockIdx.x * blockDim.x + threadIdx.x;
    if (i < n) g_dinv[i] = rsqrtf((float)g_deg[i] + 1.0f);  // +1 = self loop
}

__global__ void scan_k() {
    __shared__ int sums[1024];
    const int T = 1024;
    const int chunk = (NNODES + T - 1) / T;
    int t = threadIdx.x;
    int base = t * chunk;
    int s = 0;
    for (int j = 0; j < chunk; j++) {
        int i = base + j;
        if (i < NNODES) s += g_deg[i];
    }
    sums[t] = s;
    __syncthreads();
    for (int d = 1; d < T; d <<= 1) {
        int v = (t >= d) ? sums[t - d] : 0;
        __syncthreads();
        sums[t] += v;
        __syncthreads();
    }
    int run = (t == 0) ? 0 : sums[t - 1];
    for (int j = 0; j < chunk; j++) {
        int i = base + j;
        if (i < NNODES) {
            g_off[i] = run;
            g_cur[i] = run;
            run += g_deg[i];
        }
    }
    if (t == T - 1) g_off[NNODES] = run;
}

__global__ void csr_fill_k(const int* __restrict__ src,
                           const int* __restrict__ dst, int E) {
    int e = blockIdx.x * blockDim.x + threadIdx.x;
    if (e < E) {
        int p = atomicAdd(&g_cur[dst[e]], 1);
        g_csrc[p] = src[e];
    }
}

// Fused prep: W1^T->fp16, W2^T->fp16, x->fp16.  ONE launch (keeps gemm1 in
// the ncu capture slot).
#define PREP_W (FIN * CDIM + CDIM * CDIM)        // 262144
__global__ void prep_k(const float* __restrict__ W1,
                       const float* __restrict__ W2,
                       const float* __restrict__ x) {
    int idx = blockIdx.x * blockDim.x + threadIdx.x;
    if (idx < FIN * CDIM) {
        int n = idx & (CDIM - 1);
        int k = idx >> 8;
        g_WT1[(size_t)n * FIN + k] = __float2half_rn(W1[(size_t)k * CDIM + n]);
    } else if (idx < PREP_W) {
        int i = idx - FIN * CDIM;
        int n = i & (CDIM - 1);
        int k = i >> 8;
        g_WT2[(size_t)n * CDIM + k] = __float2half_rn(W2[(size_t)k * CDIM + n]);
    } else {
        int i = idx - PREP_W;                    // float4 index into x
        if (i < NNODES * FIN / 4) {
            float4 v = reinterpret_cast<const float4*>(x)[i];
            __half2 h01 = __floats2half2_rn(v.x, v.y);
            __half2 h23 = __floats2half2_rn(v.z, v.w);
            uint2 u;
            u.x = *reinterpret_cast<uint32_t*>(&h01);
            u.y = *reinterpret_cast<uint32_t*>(&h23);
            reinterpret_cast<uint2*>(g_xh)[i] = u;
        }
    }
}

// ---------------------------------------------------------------------------
// Ch[M,256](fp16) = A[M,K](fp16) @ WT^T(fp16), fp32 accumulate.
// 128x128 CTA tile, 8 warps (2x4), 64x32 warp tiles, cp.async 2-stage,
// mma.m16n8k16. Tiles stored as half2 pairs (uint), PITCH=20 uints/row.
// ---------------------------------------------------------------------------
__global__ __launch_bounds__(256, 2) void gemm_mma_k(
    const __half* __restrict__ A, const __half* __restrict__ WT,
    __half* __restrict__ Ch, int M, int K)
{
    __shared__ uint32_t As[2][BM * PITCH];
    __shared__ uint32_t Bs[2][BN * PITCH];

    const int tid  = threadIdx.x;
    const int lane = tid & 31;
    const int wid  = tid >> 5;
    const int wm   = wid & 1;
    const int wn   = wid >> 1;
    const int gq   = lane >> 2;
    const int cq   = lane & 3;
    const int row0 = blockIdx.y * BM;
    const int col0 = blockIdx.x * BN;

    const uint32_t asb = smem_u32(&As[0][0]);
    const uint32_t bsb = smem_u32(&Bs[0][0]);

    float acc[4][4][4];
    #pragma unroll
    for (int mt = 0; mt < 4; mt++)
        #pragma unroll
        for (int nt = 0; nt < 4; nt++)
            #pragma unroll
            for (int q = 0; q < 4; q++) acc[mt][nt][q] = 0.f;

    const int nkc = K / KCH;

    auto issue = [&](int kc, int buf) {
        const int koff = kc * KCH;               // in halfs
        #pragma unroll
        for (int t = 0; t < 2; t++) {
            int idx = tid + t * 256;             // 0..511 16B chunks
            int r   = idx >> 2;                  // row 0..127
            int c16 = idx & 3;                   // chunk within row (64B data)
            uint32_t soff = (uint32_t)(r * (PITCH * 4) + c16 * 16) + (uint32_t)buf * BUFB;
            int gr = row0 + r;
            const __half* srcA = A + (size_t)(gr < M ? gr : M - 1) * K + koff + c16 * 8;
            int nb = (gr < M) ? 16 : 0;
            asm volatile("cp.async.ca.shared.global [%0], [%1], 16, %2;"
                         :: "r"(asb + soff), "l"(srcA), "r"(nb));
            const __half* srcB = WT + (size_t)(col0 + r) * K + koff + c16 * 8;
            asm volatile("cp.async.ca.shared.global [%0], [%1], 16;"
                         :: "r"(bsb + soff), "l"(srcB));
        }
        asm volatile("cp.async.commit_group;" ::: "memory");
    };

    issue(0, 0);

    for (int kc = 0; kc < nkc; kc++) {
        const int cur = kc & 1;
        const bool more = (kc + 1) < nkc;
        if (more) {
            issue(kc + 1, cur ^ 1);
            asm volatile("cp.async.wait_group 1;" ::: "memory");
        } else {
            asm volatile("cp.async.wait_group 0;" ::: "memory");
        }
        __syncthreads();

        #pragma unroll
        for (int k0 = 0; k0 < 16; k0 += 8) {     // pair-offset: 2 k16 steps
            uint32_t bf[4][2];
            #pragma unroll
            for (int nt = 0; nt < 4; nt++) {
                int n = wn * 32 + nt * 8 + gq;
                bf[nt][0] = Bs[cur][n * PITCH + k0 + cq];
                bf[nt][1] = Bs[cur][n * PITCH + k0 + cq + 4];
            }
            #pragma unroll
            for (int mt = 0; mt < 4; mt++) {
                int r = wm * 64 + mt * 16 + gq;
                uint32_t af[4];
                af[0] = As[cur][(r    ) * PITCH + k0 + cq    ];
                af[1] = As[cur][(r + 8) * PITCH + k0 + cq    ];
                af[2] = As[cur][(r    ) * PITCH + k0 + cq + 4];
                af[3] = As[cur][(r + 8) * PITCH + k0 + cq + 4];
                #pragma unroll
                for (int nt = 0; nt < 4; nt++)
                    mma_f16(acc[mt][nt], af, bf[nt]);
            }
        }
        __syncthreads();
    }

    // epilogue: store fp16
    #pragma unroll
    for (int mt = 0; mt < 4; mt++) {
        #pragma unroll
        for (int h = 0; h < 2; h++) {
            int row = row0 + wm * 64 + mt * 16 + gq + h * 8;
            if (row < M) {
                __half* cp = Ch + (size_t)row * CDIM + col0 + wn * 32;
                #pragma unroll
                for (int nt = 0; nt < 4; nt++) {
                    __half2 o = __floats2half2_rn(acc[mt][nt][h * 2 + 0],
                                                  acc[mt][nt][h * 2 + 1]);
                    *reinterpret_cast<__half2*>(cp + nt * 8 + cq * 2) = o;
                }
            }
        }
    }
}

// ---------------------------------------------------------------------------
// Fused CSR gather (fp16 rows) + per-edge dinv[src] + self-loop + dinv[dst]
// + bias. half_out=1: relu + fp16 store (layer-1); 0: fp32 store (output).
// ---------------------------------------------------------------------------
__global__ __launch_bounds__(256) void agg_k(const float* __restrict__ b,
                                             void* __restrict__ outp,
                                             int half_out)
{
    int node = blockIdx.x * 4 + (threadIdx.x >> 6);
    if (node >= NNODES) return;
    int lane = threadIdx.x & 63;   // covers cols [lane*4, lane*4+4)

    const uint2* hs2 = reinterpret_cast<const uint2*>(g_hsh);
    float di = g_dinv[node];

    uint2 us = hs2[(size_t)node * 64 + lane];
    float2 s0 = __half22float2(*reinterpret_cast<__half2*>(&us.x));
    float2 s1 = __half22float2(*reinterpret_cast<__half2*>(&us.y));
    float4 acc;
    acc.x = s0.x * di; acc.y = s0.y * di;
    acc.z = s1.x * di; acc.w = s1.y * di;

    int j   = g_off[node];
    int end = g_off[node + 1];
    for (; j + 1 < end; j += 2) {
        int e0 = g_csrc[j];
        int e1 = g_csrc[j + 1];
        float d0 = g_dinv[e0];
        float d1 = g_dinv[e1];
        uint2 u0 = hs2[(size_t)e0 * 64 + lane];
        uint2 u1 = hs2[(size_t)e1 * 64 + lane];
        float2 a0 = __half22float2(*reinterpret_cast<__half2*>(&u0.x));
        float2 a1 = __half22float2(*reinterpret_cast<__half2*>(&u0.y));
        float2 c0 = __half22float2(*reinterpret_cast<__half2*>(&u1.x));
        float2 c1 = __half22float2(*reinterpret_cast<__half2*>(&u1.y));
        acc.x = fmaf(a0.x, d0, acc.x); acc.y = fmaf(a0.y, d0, acc.y);
        acc.z = fmaf(a1.x, d0, acc.z); acc.w = fmaf(a1.y, d0, acc.w);
        acc.x = fmaf(c0.x, d1, acc.x); acc.y = fmaf(c0.y, d1, acc.y);
        acc.z = fmaf(c1.x, d1, acc.z); acc.w = fmaf(c1.y, d1, acc.w);
    }
    if (j < end) {
        int e0 = g_csrc[j];
        float d0 = g_dinv[e0];
        uint2 u0 = hs2[(size_t)e0 * 64 + lane];
        float2 a0 = __half22float2(*reinterpret_cast<__half2*>(&u0.x));
        float2 a1 = __half22float2(*reinterpret_cast<__half2*>(&u0.y));
        acc.x = fmaf(a0.x, d0, acc.x); acc.y = fmaf(a0.y, d0, acc.y);
        acc.z = fmaf(a1.x, d0, acc.z); acc.w = fmaf(a1.y, d0, acc.w);
    }

    const float4 bb = *reinterpret_cast<const float4*>(b + lane * 4);
    float4 o;
    o.x = fmaf(acc.x, di, bb.x);
    o.y = fmaf(acc.y, di, bb.y);
    o.z = fmaf(acc.z, di, bb.z);
    o.w = fmaf(acc.w, di, bb.w);
    if (half_out) {
        // relu + fp16 (next GEMM's A operand)
        __half2 h01 = __floats2half2_rn(fmaxf(o.x, 0.f), fmaxf(o.y, 0.f));
        __half2 h23 = __floats2half2_rn(fmaxf(o.z, 0.f), fmaxf(o.w, 0.f));
        uint2 u;
        u.x = *reinterpret_cast<uint32_t*>(&h01);
        u.y = *reinterpret_cast<uint32_t*>(&h23);
        reinterpret_cast<uint2*>(outp)[(size_t)node * 64 + lane] = u;
    } else {
        reinterpret_cast<float4*>(outp)[(size_t)node * 64 + lane] = o;
    }
}

// ---------------------------------------------------------------------------
extern "C" void kernel_launch(void* const* d_in, const int* in_sizes, int n_in,
                              void* d_out, int out_size)
{
    const float* x  = (const float*)d_in[0];
    const int*   ei = (const int*)  d_in[1];
    const float* W1 = (const float*)d_in[2];
    const float* b1 = (const float*)d_in[3];
    const float* W2 = (const float*)d_in[4];
    const float* b2 = (const float*)d_in[5];
    (void)in_sizes; (void)n_in; (void)out_size;

    const int* src = ei;
    const int* dst = ei + NEDGES;

    __half *xh, *hsh, *h1h, *wt1, *wt2;
    int* degp;
    cudaGetSymbolAddress((void**)&xh,  g_xh);
    cudaGetSymbolAddress((void**)&hsh, g_hsh);
    cudaGetSymbolAddress((void**)&h1h, g_h1h);
    cudaGetSymbolAddress((void**)&wt1, g_WT1);
    cudaGetSymbolAddress((void**)&wt2, g_WT2);
    cudaGetSymbolAddress((void**)&degp, g_deg);

    // Side stream + events for fork/join inside graph capture.
    static cudaStream_t sB = nullptr;
    static cudaEvent_t evFork = nullptr, evJoin = nullptr;
    if (!sB) {
        cudaStreamCreateWithFlags(&sB, cudaStreamNonBlocking);
        cudaEventCreateWithFlags(&evFork, cudaEventDisableTiming);
        cudaEventCreateWithFlags(&evJoin, cudaEventDisableTiming);
    }

    const dim3 gemm_grid(CDIM / BN, (NNODES + BM - 1) / BM);   // (2, 391)
    const int agg_grid = (NNODES + 3) / 4;
    const int prep_threads = PREP_W + NNODES * FIN / 4;

    // Fork side stream off the main (capturing) stream.
    cudaEventRecord(evFork, 0);
    cudaStreamWaitEvent(sB, evFork, 0);

    // Main: prep (weights + x fp16) + GEMM1.  Side: CSR preprocessing.
    prep_k<<<(prep_threads + 255) / 256, 256>>>(W1, W2, x);                    // 0 main
    zero_int_k<<<(NNODES + 255) / 256, 256, 0, sB>>>(degp, NNODES);            // 1 side
    degree_k  <<<(NEDGES / 4 + 255) / 256, 256, 0, sB>>>(dst, NEDGES / 4);     // 2 side
    gemm_mma_k<<<gemm_grid, 256>>>(xh, wt1, hsh, NNODES, FIN);                 // 3 main <- ncu
    dinv_k    <<<(NNODES + 255) / 256, 256, 0, sB>>>(NNODES);                  // 4 side
    scan_k    <<<1, 1024, 0, sB>>>();                                          // 5 side
    csr_fill_k<<<(NEDGES + 255) / 256, 256, 0, sB>>>(src, dst, NEDGES);        // 6 side

    // Join: agg1 needs CSR + dinv + hs.
    cudaEventRecord(evJoin, sB);
    cudaStreamWaitEvent(0, evJoin, 0);

    agg_k<<<agg_grid, 256>>>(b1, h1h, 1);                                      // 7
    gemm_mma_k<<<gemm_grid, 256>>>(h1h, wt2, hsh, NNODES, CDIM);               // 8
    agg_k<<<agg_grid, 256>>>(b2, d_out, 0);                                    // 9
}

// round 14
// speedup vs baseline: 1.2753x; 1.0746x over previous
#include <cuda_runtime.h>
#include <cuda_fp16.h>
#include <cstdint>

#define NNODES 50000
#define NEDGES 800000
#define CDIM 256
#define FIN 768

#define BM 128
#define BN 128
#define KCH 32                    // halfs per K-chunk (2 MMA steps of k16)
#define PITCH 20                  // uints (half2 pairs) per row; conflict-free
#define BUFB (BM * PITCH * 4)     // bytes per stage buffer (10240)

// Scratch (allocation-free rule: device globals)
__device__ float  g_dinv[NNODES];
__device__ int    g_deg[NNODES];
__device__ int    g_off[NNODES + 1];
__device__ int    g_cur[NNODES];
__device__ int    g_csrc[NEDGES];
__device__ __half g_xh [NNODES * FIN];   // x converted to fp16
__device__ __half g_hsh[NNODES * CDIM];  // GEMM output h, fp16 (gather payload)
__device__ __half g_h1h[NNODES * CDIM];  // layer-1 activation, fp16
__device__ __half g_WT1[CDIM * FIN];     // W1^T fp16
__device__ __half g_WT2[CDIM * CDIM];    // W2^T fp16

__device__ __forceinline__ uint32_t smem_u32(const void* p) {
    uint32_t a;
    asm("{ .reg .u64 t; cvta.to.shared.u64 t, %1; cvt.u32.u64 %0, t; }"
        : "=r"(a) : "l"(p));
    return a;
}
__device__ __forceinline__ void mma_f16(float* c, const uint32_t* a, const uint32_t* b) {
    asm volatile(
        "mma.sync.aligned.m16n8k16.row.col.f32.f16.f16.f32 "
        "{%0,%1,%2,%3}, {%4,%5,%6,%7}, {%8,%9}, {%0,%1,%2,%3};"
        : "+f"(c[0]), "+f"(c[1]), "+f"(c[2]), "+f"(c[3])
        : "r"(a[0]), "r"(a[1]), "r"(a[2]), "r"(a[3]), "r"(b[0]), "r"(b[1]));
}

// ---------------------------------------------------------------------------
__global__ void zero_int_k(int* __restrict__ p, int n) {
    int i = blockIdx.x * blockDim.x + threadIdx.x;
    if (i < n) p[i] = 0;
}
__global__ void degree_k(const int* __restrict__ dst, int E4) {
    int i = blockIdx.x * blockDim.x + threadIdx.x;
    if (i < E4) {
        int4 d = reinterpret_cast<const int4*>(dst)[i];
        atomicAdd(&g_deg[d.x], 1);
        atomicAdd(&g_deg[d.y], 1);
        atomicAdd(&g_deg[d.z], 1);
        atomicAdd(&g_deg[d.w], 1);
    }
}
__global__ void dinv_k(int n) {
    int i = blockIdx.x * blockDim.x + threadIdx.x;
    if (i < n) g_dinv[i] = rsqrtf((float)g_deg[i] + 1.0f);  // +1 = self loop
}

__global__ void scan_k() {
    __shared__ int sums[1024];
    const int T = 1024;
    const int chunk = (NNODES + T - 1) / T;
    int t = threadIdx.x;
    int base = t * chunk;
    int s = 0;
    for (int j = 0; j < chunk; j++) {
        int i = base + j;
        if (i < NNODES) s += g_deg[i];
    }
    sums[t] = s;
    __syncthreads();
    for (int d = 1; d < T; d <<= 1) {
        int v = (t >= d) ? sums[t - d] : 0;
        __syncthreads();
        sums[t] += v;
        __syncthreads();
    }
    int run = (t == 0) ? 0 : sums[t - 1];
    for (int j = 0; j < chunk; j++) {
        int i = base + j;
        if (i < NNODES) {
            g_off[i] = run;
            g_cur[i] = run;
            run += g_deg[i];
        }
    }
    if (t == T - 1) g_off[NNODES] = run;
}

__global__ void csr_fill_k(const int* __restrict__ src,
                           const int* __restrict__ dst, int E) {
    int e = blockIdx.x * blockDim.x + threadIdx.x;
    if (e < E) {
        int p = atomicAdd(&g_cur[dst[e]], 1);
        g_csrc[p] = src[e];
    }
}

// Fused prep: W1^T->fp16, W2^T->fp16, x->fp16.
#define PREP_W (FIN * CDIM + CDIM * CDIM)        // 262144
__global__ void prep_k(const float* __restrict__ W1,
                       const float* __restrict__ W2,
                       const float* __restrict__ x) {
    int idx = blockIdx.x * blockDim.x + threadIdx.x;
    if (idx < FIN * CDIM) {
        int n = idx & (CDIM - 1);
        int k = idx >> 8;
        g_WT1[(size_t)n * FIN + k] = __float2half_rn(W1[(size_t)k * CDIM + n]);
    } else if (idx < PREP_W) {
        int i = idx - FIN * CDIM;
        int n = i & (CDIM - 1);
        int k = i >> 8;
        g_WT2[(size_t)n * CDIM + k] = __float2half_rn(W2[(size_t)k * CDIM + n]);
    } else {
        int i = idx - PREP_W;                    // float4 index into x
        if (i < NNODES * FIN / 4) {
            float4 v = reinterpret_cast<const float4*>(x)[i];
            __half2 h01 = __floats2half2_rn(v.x, v.y);
            __half2 h23 = __floats2half2_rn(v.z, v.w);
            uint2 u;
            u.x = *reinterpret_cast<uint32_t*>(&h01);
            u.y = *reinterpret_cast<uint32_t*>(&h23);
            reinterpret_cast<uint2*>(g_xh)[i] = u;
        }
    }
}

// ---------------------------------------------------------------------------
// Ch[M,256](fp16) = A[M,K](fp16) @ WT^T(fp16), fp32 accumulate.
// 128x128 CTA tile, 8 warps (2x4), 64x32 warp tiles, cp.async 2-stage,
// mma.m16n8k16.
// ---------------------------------------------------------------------------
__global__ __launch_bounds__(256, 2) void gemm_mma_k(
    const __half* __restrict__ A, const __half* __restrict__ WT,
    __half* __restrict__ Ch, int M, int K)
{
    __shared__ uint32_t As[2][BM * PITCH];
    __shared__ uint32_t Bs[2][BN * PITCH];

    const int tid  = threadIdx.x;
    const int lane = tid & 31;
    const int wid  = tid >> 5;
    const int wm   = wid & 1;
    const int wn   = wid >> 1;
    const int gq   = lane >> 2;
    const int cq   = lane & 3;
    const int row0 = blockIdx.y * BM;
    const int col0 = blockIdx.x * BN;

    const uint32_t asb = smem_u32(&As[0][0]);
    const uint32_t bsb = smem_u32(&Bs[0][0]);

    float acc[4][4][4];
    #pragma unroll
    for (int mt = 0; mt < 4; mt++)
        #pragma unroll
        for (int nt = 0; nt < 4; nt++)
            #pragma unroll
            for (int q = 0; q < 4; q++) acc[mt][nt][q] = 0.f;

    const int nkc = K / KCH;

    auto issue = [&](int kc, int buf) {
        const int koff = kc * KCH;               // in halfs
        #pragma unroll
        for (int t = 0; t < 2; t++) {
            int idx = tid + t * 256;             // 0..511 16B chunks
            int r   = idx >> 2;                  // row 0..127
            int c16 = idx & 3;                   // chunk within row
            uint32_t soff = (uint32_t)(r * (PITCH * 4) + c16 * 16) + (uint32_t)buf * BUFB;
            int gr = row0 + r;
            const __half* srcA = A + (size_t)(gr < M ? gr : M - 1) * K + koff + c16 * 8;
            int nb = (gr < M) ? 16 : 0;
            asm volatile("cp.async.ca.shared.global [%0], [%1], 16, %2;"
                         :: "r"(asb + soff), "l"(srcA), "r"(nb));
            const __half* srcB = WT + (size_t)(col0 + r) * K + koff + c16 * 8;
            asm volatile("cp.async.ca.shared.global [%0], [%1], 16;"
                         :: "r"(bsb + soff), "l"(srcB));
        }
        asm volatile("cp.async.commit_group;" ::: "memory");
    };

    issue(0, 0);

    for (int kc = 0; kc < nkc; kc++) {
        const int cur = kc & 1;
        const bool more = (kc + 1) < nkc;
        if (more) {
            issue(kc + 1, cur ^ 1);
            asm volatile("cp.async.wait_group 1;" ::: "memory");
        } else {
            asm volatile("cp.async.wait_group 0;" ::: "memory");
        }
        __syncthreads();

        #pragma unroll
        for (int k0 = 0; k0 < 16; k0 += 8) {     // 2 k16 steps
            uint32_t bf[4][2];
            #pragma unroll
            for (int nt = 0; nt < 4; nt++) {
                int n = wn * 32 + nt * 8 + gq;
                bf[nt][0] = Bs[cur][n * PITCH + k0 + cq];
                bf[nt][1] = Bs[cur][n * PITCH + k0 + cq + 4];
            }
            #pragma unroll
            for (int mt = 0; mt < 4; mt++) {
                int r = wm * 64 + mt * 16 + gq;
                uint32_t af[4];
                af[0] = As[cur][(r    ) * PITCH + k0 + cq    ];
                af[1] = As[cur][(r + 8) * PITCH + k0 + cq    ];
                af[2] = As[cur][(r    ) * PITCH + k0 + cq + 4];
                af[3] = As[cur][(r + 8) * PITCH + k0 + cq + 4];
                #pragma unroll
                for (int nt = 0; nt < 4; nt++)
                    mma_f16(acc[mt][nt], af, bf[nt]);
            }
        }
        __syncthreads();
    }

    // epilogue: store fp16
    #pragma unroll
    for (int mt = 0; mt < 4; mt++) {
        #pragma unroll
        for (int h = 0; h < 2; h++) {
            int row = row0 + wm * 64 + mt * 16 + gq + h * 8;
            if (row < M) {
                __half* cp = Ch + (size_t)row * CDIM + col0 + wn * 32;
                #pragma unroll
                for (int nt = 0; nt < 4; nt++) {
                    __half2 o = __floats2half2_rn(acc[mt][nt][h * 2 + 0],
                                                  acc[mt][nt][h * 2 + 1]);
                    *reinterpret_cast<__half2*>(cp + nt * 8 + cq * 2) = o;
                }
            }
        }
    }
}

// ---------------------------------------------------------------------------
// Fused CSR gather: ONE WARP per node, uint4 (8 halfs) per lane = full row.
// 4-edge unroll -> 4 outstanding LDG.128 per lane (MLP 4). fp32 accumulate.
// out[i] = act((sum_s h[s]*d[s] + h[i]*d[i]) * d[i] + b)
// ---------------------------------------------------------------------------
__device__ __forceinline__ void acc_row(float* acc, uint4 u, float d) {
    float2 f0 = __half22float2(*reinterpret_cast<__half2*>(&u.x));
    float2 f1 = __half22float2(*reinterpret_cast<__half2*>(&u.y));
    float2 f2 = __half22float2(*reinterpret_cast<__half2*>(&u.z));
    float2 f3 = __half22float2(*reinterpret_cast<__half2*>(&u.w));
    acc[0] = fmaf(f0.x, d, acc[0]); acc[1] = fmaf(f0.y, d, acc[1]);
    acc[2] = fmaf(f1.x, d, acc[2]); acc[3] = fmaf(f1.y, d, acc[3]);
    acc[4] = fmaf(f2.x, d, acc[4]); acc[5] = fmaf(f2.y, d, acc[5]);
    acc[6] = fmaf(f3.x, d, acc[6]); acc[7] = fmaf(f3.y, d, acc[7]);
}

__global__ __launch_bounds__(256) void agg_k(const float* __restrict__ b,
                                             void* __restrict__ outp,
                                             int half_out)
{
    int node = blockIdx.x * 8 + (threadIdx.x >> 5);   // warp per node
    if (node >= NNODES) return;
    int lane = threadIdx.x & 31;   // covers halfs [lane*8, lane*8+8)

    const uint4* hs4 = reinterpret_cast<const uint4*>(g_hsh);  // 32 uint4/row
    float di = g_dinv[node];

    float acc[8];
    {
        uint4 us = hs4[(size_t)node * 32 + lane];
        #pragma unroll
        for (int q = 0; q < 8; q++) acc[q] = 0.f;
        acc_row(acc, us, di);                      // self loop
    }

    int j   = g_off[node];
    int end = g_off[node + 1];
    for (; j + 3 < end; j += 4) {
        int e0 = g_csrc[j];
        int e1 = g_csrc[j + 1];
        int e2 = g_csrc[j + 2];
        int e3 = g_csrc[j + 3];
        float d0 = g_dinv[e0];
        float d1 = g_dinv[e1];
        float d2 = g_dinv[e2];
        float d3 = g_dinv[e3];
        uint4 u0 = hs4[(size_t)e0 * 32 + lane];
        uint4 u1 = hs4[(size_t)e1 * 32 + lane];
        uint4 u2 = hs4[(size_t)e2 * 32 + lane];
        uint4 u3 = hs4[(size_t)e3 * 32 + lane];
        acc_row(acc, u0, d0);
        acc_row(acc, u1, d1);
        acc_row(acc, u2, d2);
        acc_row(acc, u3, d3);
    }
    for (; j < end; j++) {
        int e0 = g_csrc[j];
        float d0 = g_dinv[e0];
        uint4 u0 = hs4[(size_t)e0 * 32 + lane];
        acc_row(acc, u0, d0);
    }

    const float4 b0 = *reinterpret_cast<const float4*>(b + lane * 8);
    const float4 b1 = *reinterpret_cast<const float4*>(b + lane * 8 + 4);
    float o[8];
    o[0] = fmaf(acc[0], di, b0.x); o[1] = fmaf(acc[1], di, b0.y);
    o[2] = fmaf(acc[2], di, b0.z); o[3] = fmaf(acc[3], di, b0.w);
    o[4] = fmaf(acc[4], di, b1.x); o[5] = fmaf(acc[5], di, b1.y);
    o[6] = fmaf(acc[6], di, b1.z); o[7] = fmaf(acc[7], di, b1.w);

    if (half_out) {
        #pragma unroll
        for (int q = 0; q < 8; q++) o[q] = fmaxf(o[q], 0.f);
        __half2 h0 = __floats2half2_rn(o[0], o[1]);
        __half2 h1 = __floats2half2_rn(o[2], o[3]);
        __half2 h2 = __floats2half2_rn(o[4], o[5]);
        __half2 h3 = __floats2half2_rn(o[6], o[7]);
        uint4 u;
        u.x = *reinterpret_cast<uint32_t*>(&h0);
        u.y = *reinterpret_cast<uint32_t*>(&h1);
        u.z = *reinterpret_cast<uint32_t*>(&h2);
        u.w = *reinterpret_cast<uint32_t*>(&h3);
        reinterpret_cast<uint4*>(outp)[(size_t)node * 32 + lane] = u;
    } else {
        float4* op = reinterpret_cast<float4*>(outp) + (size_t)node * 64 + lane * 2;
        op[0] = make_float4(o[0], o[1], o[2], o[3]);
        op[1] = make_float4(o[4], o[5], o[6], o[7]);
    }
}

// ---------------------------------------------------------------------------
extern "C" void kernel_launch(void* const* d_in, const int* in_sizes, int n_in,
                              void* d_out, int out_size)
{
    const float* x  = (const float*)d_in[0];
    const int*   ei = (const int*)  d_in[1];
    const float* W1 = (const float*)d_in[2];
    const float* b1 = (const float*)d_in[3];
    const float* W2 = (const float*)d_in[4];
    const float* b2 = (const float*)d_in[5];
    (void)in_sizes; (void)n_in; (void)out_size;

    const int* src = ei;
    const int* dst = ei + NEDGES;

    __half *xh, *hsh, *h1h, *wt1, *wt2;
    int* degp;
    cudaGetSymbolAddress((void**)&xh,  g_xh);
    cudaGetSymbolAddress((void**)&hsh, g_hsh);
    cudaGetSymbolAddress((void**)&h1h, g_h1h);
    cudaGetSymbolAddress((void**)&wt1, g_WT1);
    cudaGetSymbolAddress((void**)&wt2, g_WT2);
    cudaGetSymbolAddress((void**)&degp, g_deg);

    // Side stream + events for fork/join inside graph capture.
    static cudaStream_t sB = nullptr;
    static cudaEvent_t evFork = nullptr, evJoin = nullptr;
    if (!sB) {
        cudaStreamCreateWithFlags(&sB, cudaStreamNonBlocking);
        cudaEventCreateWithFlags(&evFork, cudaEventDisableTiming);
        cudaEventCreateWithFlags(&evJoin, cudaEventDisableTiming);
    }

    const dim3 gemm_grid(CDIM / BN, (NNODES + BM - 1) / BM);   // (2, 391)
    const int agg_grid = (NNODES + 7) / 8;                     // warp/node
    const int prep_threads = PREP_W + NNODES * FIN / 4;

    // Fork side stream off the main (capturing) stream.
    cudaEventRecord(evFork, 0);
    cudaStreamWaitEvent(sB, evFork, 0);

    // Main: prep (weights + x fp16) + GEMM1.  Side: CSR preprocessing.
    prep_k<<<(prep_threads + 255) / 256, 256>>>(W1, W2, x);                    // 0 main
    zero_int_k<<<(NNODES + 255) / 256, 256, 0, sB>>>(degp, NNODES);            // 1 side
    degree_k  <<<(NEDGES / 4 + 255) / 256, 256, 0, sB>>>(dst, NEDGES / 4);     // 2 side
    gemm_mma_k<<<gemm_grid, 256>>>(xh, wt1, hsh, NNODES, FIN);                 // 3 main <- ncu
    dinv_k    <<<(NNODES + 255) / 256, 256, 0, sB>>>(NNODES);                  // 4 side
    scan_k    <<<1, 1024, 0, sB>>>();                                          // 5 side
    csr_fill_k<<<(NEDGES + 255) / 256, 256, 0, sB>>>(src, dst, NEDGES);        // 6 side

    // Join: agg1 needs CSR + dinv + hs.
    cudaEventRecord(evJoin, sB);
    cudaStreamWaitEvent(0, evJoin, 0);

    agg_k<<<agg_grid, 256>>>(b1, h1h, 1);                                      // 7
    gemm_mma_k<<<gemm_grid, 256>>>(h1h, wt2, hsh, NNODES, CDIM);               // 8
    agg_k<<<agg_grid, 256>>>(b2, d_out, 0);                                    // 9
}